// round 1
// baseline (speedup 1.0000x reference)
#include <cuda_runtime.h>
#include <cuda_bf16.h>
#include <cstdint>

// ---------------------------------------------------------------------------
// Problem constants (shapes are fixed by the reference; guarded at runtime)
// ---------------------------------------------------------------------------
#define NNODES_MAX 8192
#define E_MAX      131072
#define EF_MAX     (E_MAX / 2)      // forward edges (src < dst)
#define HID        768
#define PPRODS     83
#define MSG        249              // NDIM * PPRODS
#define NDIM       3

// ---------------------------------------------------------------------------
// Scratch (static __device__ BSS; no runtime allocation)
// ---------------------------------------------------------------------------
__device__ float g_h1[(size_t)EF_MAX * HID];     // 192 MB
__device__ float g_h2[(size_t)EF_MAX * HID];     // 192 MB
__device__ float g_w [(size_t)EF_MAX * MSG];     // 64 MB
__device__ float g_prods[(size_t)EF_MAX * PPRODS];
__device__ float g_agg[NNODES_MAX * NDIM];
__device__ int   g_fwd_e[EF_MAX];
__device__ int   g_fwd_src[EF_MAX];
__device__ int   g_fwd_dst[EF_MAX];
__device__ int   g_cnt;

__device__ __forceinline__ float leaky(float v) { return v > 0.f ? v : 0.01f * v; }

// ---------------------------------------------------------------------------
// K0: zero agg + counter
// ---------------------------------------------------------------------------
__global__ void k_zero(int nAgg) {
    int i = blockIdx.x * blockDim.x + threadIdx.x;
    if (i < nAgg) g_agg[i] = 0.f;
    if (i == 0) g_cnt = 0;
}

// ---------------------------------------------------------------------------
// K_compact: collect forward edges (src < dst)
// ---------------------------------------------------------------------------
__global__ void k_compact(const int* __restrict__ src, const int* __restrict__ dst, int E) {
    int e = blockIdx.x * blockDim.x + threadIdx.x;
    if (e >= E) return;
    int s = src[e], d = dst[e];
    if (s < d) {
        int i = atomicAdd(&g_cnt, 1);
        if (i < EF_MAX) { g_fwd_e[i] = e; g_fwd_src[i] = s; g_fwd_dst[i] = d; }
    }
}

// ---------------------------------------------------------------------------
// K1: h1 = leaky(edge_attr @ W1 + b1)  and polynomial products
//     warp-per-edge; W1/b1 staged in smem
// ---------------------------------------------------------------------------
__global__ __launch_bounds__(256) void k_h1_prods(
    const float* __restrict__ edge_attr,
    const float* __restrict__ W1, const float* __restrict__ b1, int EF)
{
    __shared__ float sW1[6 * HID];
    __shared__ float sb1[HID];
    int tid = threadIdx.x;
    for (int i = tid; i < 6 * HID; i += blockDim.x) sW1[i] = W1[i];
    for (int i = tid; i < HID;     i += blockDim.x) sb1[i] = b1[i];
    __syncthreads();

    int warp = tid >> 5, lane = tid & 31;
    int s = blockIdx.x * 8 + warp;
    if (s >= EF) return;
    int e = g_fwd_e[s];

    float a[6];
#pragma unroll
    for (int i = 0; i < 6; i++) a[i] = edge_attr[e * 6 + i];

    float* h1r = g_h1 + (size_t)s * HID;
    for (int j = lane; j < HID; j += 32) {
        float acc = sb1[j];
#pragma unroll
        for (int i = 0; i < 6; i++) acc += a[i] * sW1[i * HID + j];
        h1r[j] = leaky(acc);
    }

    if (lane == 0) {
        float* pp = g_prods + (size_t)s * PPRODS;
        int p = 0;
#pragma unroll
        for (int i = 0; i < 6; i++) pp[p++] = a[i];
#pragma unroll
        for (int i = 0; i < 6; i++)
            for (int j = i; j < 6; j++) pp[p++] = a[i] * a[j];
#pragma unroll
        for (int i = 0; i < 6; i++)
            for (int j = i; j < 6; j++)
                for (int k = j; k < 6; k++) pp[p++] = a[i] * a[j] * a[k];
    }
}

// ---------------------------------------------------------------------------
// sgemm: C[M,N] = act(A[M,K] @ B[K,N] + bias)   (row-major, BM=BN=128, BK=8)
// 256 threads, 8x8 microtile per thread
// ---------------------------------------------------------------------------
__global__ __launch_bounds__(256) void sgemm128(
    const float* __restrict__ A, const float* __restrict__ B,
    const float* __restrict__ bias, float* __restrict__ C,
    int M, int N, int K, int doRelu)
{
    __shared__ float As[8][128];
    __shared__ float Bs[8][128];

    const int tid  = threadIdx.x;
    const int tx   = tid & 15;        // 0..15 -> N
    const int ty   = tid >> 4;        // 0..15 -> M
    const int row0 = blockIdx.y * 128;
    const int col0 = blockIdx.x * 128;

    // A loads: one float4 per thread, rows 0..127, cols {0,4}
    const int aRow = tid >> 1;
    const int aCol = (tid & 1) * 4;
    // B loads: 4 scalars per thread, rows 0..7, cols (tid&31)*4..+3
    const int bRow = tid >> 5;
    const int bCol = (tid & 31) * 4;

    float acc[8][8];
#pragma unroll
    for (int i = 0; i < 8; i++)
#pragma unroll
        for (int j = 0; j < 8; j++) acc[i][j] = 0.f;

    for (int k0 = 0; k0 < K; k0 += 8) {
        // stage A (transposed into As[k][m])
        {
            int r = row0 + aRow;
            float4 v = make_float4(0.f, 0.f, 0.f, 0.f);
            if (r < M) v = *(const float4*)(A + (size_t)r * K + k0 + aCol);
            As[aCol + 0][aRow] = v.x;
            As[aCol + 1][aRow] = v.y;
            As[aCol + 2][aRow] = v.z;
            As[aCol + 3][aRow] = v.w;
        }
        // stage B (scalar, guarded for N=249)
        {
            const float* Bp = B + (size_t)(k0 + bRow) * N;
#pragma unroll
            for (int q = 0; q < 4; q++) {
                int c = col0 + bCol + q;
                Bs[bRow][bCol + q] = (c < N) ? Bp[c] : 0.f;
            }
        }
        __syncthreads();

#pragma unroll
        for (int k = 0; k < 8; k++) {
            float ar[8], br[8];
#pragma unroll
            for (int i = 0; i < 8; i++) ar[i] = As[k][ty * 8 + i];
#pragma unroll
            for (int j = 0; j < 8; j++) br[j] = Bs[k][tx * 8 + j];
#pragma unroll
            for (int i = 0; i < 8; i++)
#pragma unroll
                for (int j = 0; j < 8; j++) acc[i][j] += ar[i] * br[j];
        }
        __syncthreads();
    }

#pragma unroll
    for (int i = 0; i < 8; i++) {
        int r = row0 + ty * 8 + i;
        if (r >= M) continue;
        float* Cr = C + (size_t)r * N;
#pragma unroll
        for (int j = 0; j < 8; j++) {
            int c = col0 + tx * 8 + j;
            if (c < N) {
                float v = acc[i][j] + bias[c];
                if (doRelu) v = leaky(v);
                Cr[c] = v;
            }
        }
    }
}

// ---------------------------------------------------------------------------
// K4: res[k] = sum_p w[k*83+p]*prods[p]; antisymmetric scatter-add
//     warp-per-edge with shuffle reduction
// ---------------------------------------------------------------------------
__global__ __launch_bounds__(256) void k_einsum_scatter(int EF) {
    int tid = threadIdx.x;
    int warp = tid >> 5, lane = tid & 31;
    int s = blockIdx.x * 8 + warp;
    if (s >= EF) return;

    const float* wr = g_w     + (size_t)s * MSG;
    const float* pr = g_prods + (size_t)s * PPRODS;
    float r0 = 0.f, r1 = 0.f, r2 = 0.f;
    for (int p = lane; p < PPRODS; p += 32) {
        float pv = pr[p];
        r0 += wr[p] * pv;
        r1 += wr[PPRODS + p] * pv;
        r2 += wr[2 * PPRODS + p] * pv;
    }
#pragma unroll
    for (int off = 16; off > 0; off >>= 1) {
        r0 += __shfl_down_sync(0xffffffffu, r0, off);
        r1 += __shfl_down_sync(0xffffffffu, r1, off);
        r2 += __shfl_down_sync(0xffffffffu, r2, off);
    }
    if (lane == 0) {
        int d = g_fwd_dst[s], sn = g_fwd_src[s];
        atomicAdd(&g_agg[d * 3 + 0],  r0);
        atomicAdd(&g_agg[d * 3 + 1],  r1);
        atomicAdd(&g_agg[d * 3 + 2],  r2);
        atomicAdd(&g_agg[sn * 3 + 0], -r0);
        atomicAdd(&g_agg[sn * 3 + 1], -r1);
        atomicAdd(&g_agg[sn * 3 + 2], -r2);
    }
}

// ---------------------------------------------------------------------------
// K5: per-node LayerNorm(cat(x, agg)) -> MLP 19->18->17->16
// ---------------------------------------------------------------------------
__global__ __launch_bounds__(128) void k_update(
    const float* __restrict__ x,
    const float* __restrict__ ln_g, const float* __restrict__ ln_b,
    const float* __restrict__ uW1, const float* __restrict__ ub1,
    const float* __restrict__ uW2, const float* __restrict__ ub2,
    const float* __restrict__ uW3, const float* __restrict__ ub3,
    float* __restrict__ out, int N)
{
    int n = blockIdx.x * blockDim.x + threadIdx.x;
    if (n >= N) return;

    float h[19];
#pragma unroll
    for (int i = 0; i < 16; i++) h[i] = x[n * 16 + i];
#pragma unroll
    for (int k = 0; k < 3; k++) h[16 + k] = g_agg[n * 3 + k];

    float mu = 0.f;
#pragma unroll
    for (int i = 0; i < 19; i++) mu += h[i];
    mu *= (1.f / 19.f);
    float var = 0.f;
#pragma unroll
    for (int i = 0; i < 19; i++) { float d = h[i] - mu; var += d * d; }
    var *= (1.f / 19.f);
    float rstd = rsqrtf(var + 1e-5f);

    float hn[19];
#pragma unroll
    for (int i = 0; i < 19; i++) hn[i] = (h[i] - mu) * rstd * ln_g[i] + ln_b[i];

    float t1[18];
#pragma unroll
    for (int o = 0; o < 18; o++) {
        float acc = ub1[o];
#pragma unroll
        for (int i = 0; i < 19; i++) acc += hn[i] * uW1[i * 18 + o];
        t1[o] = leaky(acc);
    }
    float t2[17];
#pragma unroll
    for (int o = 0; o < 17; o++) {
        float acc = ub2[o];
#pragma unroll
        for (int i = 0; i < 18; i++) acc += t1[i] * uW2[i * 17 + o];
        t2[o] = leaky(acc);
    }
#pragma unroll
    for (int o = 0; o < 16; o++) {
        float acc = ub3[o];
#pragma unroll
        for (int i = 0; i < 17; i++) acc += t2[i] * uW3[i * 16 + o];
        out[n * 16 + o] = acc;
    }
}

// ---------------------------------------------------------------------------
// launch
// ---------------------------------------------------------------------------
extern "C" void kernel_launch(void* const* d_in, const int* in_sizes, int n_in,
                              void* d_out, int out_size)
{
    const float* x    = (const float*)d_in[0];
    const float* ea   = (const float*)d_in[1];
    const float* mW1  = (const float*)d_in[2];
    const float* mb1  = (const float*)d_in[3];
    const float* mW2  = (const float*)d_in[4];
    const float* mb2  = (const float*)d_in[5];
    const float* mW3  = (const float*)d_in[6];
    const float* mb3  = (const float*)d_in[7];
    const float* ln_g = (const float*)d_in[8];
    const float* ln_b = (const float*)d_in[9];
    const float* uW1  = (const float*)d_in[10];
    const float* ub1  = (const float*)d_in[11];
    const float* uW2  = (const float*)d_in[12];
    const float* ub2  = (const float*)d_in[13];
    const float* uW3  = (const float*)d_in[14];
    const float* ub3  = (const float*)d_in[15];
    const int*   ei   = (const int*)d_in[16];
    float* out = (float*)d_out;

    const int N  = in_sizes[0] / 16;     // 8192 nodes
    const int E  = in_sizes[1] / 6;      // 131072 edges
    int EF = E / 2;                      // forward edges
    if (EF > EF_MAX) EF = EF_MAX;

    const int* src = ei;
    const int* dst = ei + E;

    // device pointers for scratch used by sgemm launches
    float *p_h1, *p_h2, *p_w;
    cudaGetSymbolAddress((void**)&p_h1, g_h1);
    cudaGetSymbolAddress((void**)&p_h2, g_h2);
    cudaGetSymbolAddress((void**)&p_w,  g_w);

    // K0: zero agg + counter
    {
        int n = N * 3;
        k_zero<<<(n + 255) / 256, 256>>>(n);
    }
    // compact forward edges
    k_compact<<<(E + 255) / 256, 256>>>(src, dst, E);

    // K1: first layer + poly products (warp per edge, 8 edges/block)
    k_h1_prods<<<(EF + 7) / 8, 256>>>(ea, mW1, mb1, EF);

    // GEMM2: h2 = leaky(h1 @ mW2 + mb2)   [EF,768]x[768,768]
    {
        dim3 grid((HID + 127) / 128, (EF + 127) / 128);
        sgemm128<<<grid, 256>>>(p_h1, mW2, mb2, p_h2, EF, HID, HID, 1);
    }
    // GEMM3: w = h2 @ mW3 + mb3           [EF,768]x[768,249]
    {
        dim3 grid((MSG + 127) / 128, (EF + 127) / 128);
        sgemm128<<<grid, 256>>>(p_h2, mW3, mb3, p_w, EF, MSG, HID, 0);
    }
    // K4: einsum + antisymmetric scatter
    k_einsum_scatter<<<(EF + 7) / 8, 256>>>(EF);

    // K5: node update
    k_update<<<(N + 127) / 128, 128>>>(x, ln_g, ln_b, uW1, ub1, uW2, ub2, uW3, ub3, out, N);
}

// round 3
// speedup vs baseline: 2.2689x; 2.2689x over previous
#include <cuda_runtime.h>
#include <cuda_bf16.h>
#include <cstdint>

// ---------------------------------------------------------------------------
// Problem constants
// ---------------------------------------------------------------------------
#define NNODES_MAX 8192
#define E_MAX      131072
#define EF_MAX     (E_MAX / 2)
#define HID        768
#define PPRODS     83
#define MSG        249
#define NDIM       3

// ---------------------------------------------------------------------------
// Scratch (static __device__ BSS)
// ---------------------------------------------------------------------------
__device__ float g_h1[(size_t)EF_MAX * HID];
__device__ float g_h2[(size_t)EF_MAX * HID];
__device__ float g_w [(size_t)EF_MAX * MSG];
__device__ float g_prods[(size_t)EF_MAX * PPRODS];
__device__ float g_agg[NNODES_MAX * NDIM];
__device__ float g_w2t[HID * HID];      // mW2^T  [N=768][K=768]
__device__ float g_w3t[MSG * HID];      // mW3^T  [N=249][K=768]
__device__ int   g_fwd_e[EF_MAX];
__device__ int   g_fwd_src[EF_MAX];
__device__ int   g_fwd_dst[EF_MAX];
__device__ int   g_cnt;

__device__ __forceinline__ float leaky(float v) { return v > 0.f ? v : 0.01f * v; }

__device__ __forceinline__ uint32_t f2tf32(float x) {
    uint32_t r;
    asm("cvt.rna.tf32.f32 %0, %1;" : "=r"(r) : "f"(x));
    return r;
}

// ---------------------------------------------------------------------------
// Small kernels
// ---------------------------------------------------------------------------
__global__ void k_zero(int nAgg) {
    int i = blockIdx.x * blockDim.x + threadIdx.x;
    if (i < nAgg) g_agg[i] = 0.f;
    if (i == 0) g_cnt = 0;
}

__global__ void k_compact(const int* __restrict__ src, const int* __restrict__ dst, int E) {
    int e = blockIdx.x * blockDim.x + threadIdx.x;
    if (e >= E) return;
    int s = src[e], d = dst[e];
    if (s < d) {
        int i = atomicAdd(&g_cnt, 1);
        if (i < EF_MAX) { g_fwd_e[i] = e; g_fwd_src[i] = s; g_fwd_dst[i] = d; }
    }
}

__global__ __launch_bounds__(256) void k_h1_prods(
    const float* __restrict__ edge_attr,
    const float* __restrict__ W1, const float* __restrict__ b1, int EF)
{
    __shared__ float sW1[6 * HID];
    __shared__ float sb1[HID];
    int tid = threadIdx.x;
    for (int i = tid; i < 6 * HID; i += blockDim.x) sW1[i] = W1[i];
    for (int i = tid; i < HID;     i += blockDim.x) sb1[i] = b1[i];
    __syncthreads();

    int warp = tid >> 5, lane = tid & 31;
    int s = blockIdx.x * 8 + warp;
    if (s >= EF) return;
    int e = g_fwd_e[s];

    float a[6];
#pragma unroll
    for (int i = 0; i < 6; i++) a[i] = edge_attr[e * 6 + i];

    float* h1r = g_h1 + (size_t)s * HID;
    for (int j = lane; j < HID; j += 32) {
        float acc = sb1[j];
#pragma unroll
        for (int i = 0; i < 6; i++) acc += a[i] * sW1[i * HID + j];
        h1r[j] = leaky(acc);
    }

    if (lane == 0) {
        float* pp = g_prods + (size_t)s * PPRODS;
        int p = 0;
#pragma unroll
        for (int i = 0; i < 6; i++) pp[p++] = a[i];
#pragma unroll
        for (int i = 0; i < 6; i++)
            for (int j = i; j < 6; j++) pp[p++] = a[i] * a[j];
#pragma unroll
        for (int i = 0; i < 6; i++)
            for (int j = i; j < 6; j++)
                for (int k = j; k < 6; k++) pp[p++] = a[i] * a[j] * a[k];
    }
}

// tiled transpose: Wt[n*K_ld + k] = W[k*N + n]
__global__ void k_transpose(const float* __restrict__ W, float* __restrict__ Wt,
                            int K, int N, int K_ld)
{
    __shared__ float t[32][33];
    int kb = blockIdx.y * 32, nb = blockIdx.x * 32;
    int tx = threadIdx.x, ty = threadIdx.y;
    for (int i = ty; i < 32; i += 8) {
        int k = kb + i, n = nb + tx;
        t[i][tx] = (k < K && n < N) ? W[(size_t)k * N + n] : 0.f;
    }
    __syncthreads();
    for (int i = ty; i < 32; i += 8) {
        int n = nb + i, k = kb + tx;
        if (n < N && k < K) Wt[(size_t)n * K_ld + k] = t[tx][i];
    }
}

// ---------------------------------------------------------------------------
// tf32 mma.sync GEMM: C[M,N] = act(A[M,K] @ Bt[N,K]^T + bias)
// BM=BN=128, BK=16, 8 warps (4 M x 2 N), warp tile 32x64, m16n8k8.
// ---------------------------------------------------------------------------
#define SA 20   // smem row stride in floats (conflict-free fragment loads)

__device__ __forceinline__ void mma1688(float* c, const uint32_t* a, const uint32_t* b) {
    asm volatile(
        "mma.sync.aligned.m16n8k8.row.col.f32.tf32.tf32.f32 "
        "{%0,%1,%2,%3}, {%4,%5,%6,%7}, {%8,%9}, {%0,%1,%2,%3};"
        : "+f"(c[0]), "+f"(c[1]), "+f"(c[2]), "+f"(c[3])
        : "r"(a[0]), "r"(a[1]), "r"(a[2]), "r"(a[3]), "r"(b[0]), "r"(b[1]));
}

__global__ __launch_bounds__(256, 2) void gemm_mma(
    const float* __restrict__ A, const float* __restrict__ Bt,
    const float* __restrict__ bias, float* __restrict__ C,
    int M, int N, int K, int doRelu)
{
    __shared__ float As[128][SA];
    __shared__ float Bs[128][SA];

    const int tid  = threadIdx.x;
    const int wid  = tid >> 5;
    const int lane = tid & 31;
    const int g    = lane >> 2;      // 0..7
    const int tig  = lane & 3;       // 0..3
    const int wm   = wid & 3;        // 0..3  -> M
    const int wn   = wid >> 2;       // 0..1  -> N
    const int row0 = blockIdx.y * 128;
    const int col0 = blockIdx.x * 128;

    // staging map: each thread loads 8 floats of one row (A) and one row (B)
    const int sm = tid >> 1;          // 0..127
    const int sk = (tid & 1) * 8;     // 0 or 8
    const bool aV = (row0 + sm) < M;
    const bool bV = (col0 + sm) < N;
    const float* Ag = A  + (size_t)(row0 + sm) * K + sk;
    const float* Bg = Bt + (size_t)(col0 + sm) * K + sk;

    float acc[2][8][4];
#pragma unroll
    for (int mi = 0; mi < 2; mi++)
#pragma unroll
        for (int ni = 0; ni < 8; ni++)
#pragma unroll
            for (int q = 0; q < 4; q++) acc[mi][ni][q] = 0.f;

    const int nCh = K / 16;
    float4 ra0, ra1, rb0, rb1;
    const float4 z4 = make_float4(0.f, 0.f, 0.f, 0.f);

    ra0 = aV ? *(const float4*)(Ag)     : z4;
    ra1 = aV ? *(const float4*)(Ag + 4) : z4;
    rb0 = bV ? *(const float4*)(Bg)     : z4;
    rb1 = bV ? *(const float4*)(Bg + 4) : z4;

    for (int c = 0; c < nCh; ++c) {
        // stage (convert to tf32 bits)
        As[sm][sk + 0] = __uint_as_float(f2tf32(ra0.x));
        As[sm][sk + 1] = __uint_as_float(f2tf32(ra0.y));
        As[sm][sk + 2] = __uint_as_float(f2tf32(ra0.z));
        As[sm][sk + 3] = __uint_as_float(f2tf32(ra0.w));
        As[sm][sk + 4] = __uint_as_float(f2tf32(ra1.x));
        As[sm][sk + 5] = __uint_as_float(f2tf32(ra1.y));
        As[sm][sk + 6] = __uint_as_float(f2tf32(ra1.z));
        As[sm][sk + 7] = __uint_as_float(f2tf32(ra1.w));
        Bs[sm][sk + 0] = __uint_as_float(f2tf32(rb0.x));
        Bs[sm][sk + 1] = __uint_as_float(f2tf32(rb0.y));
        Bs[sm][sk + 2] = __uint_as_float(f2tf32(rb0.z));
        Bs[sm][sk + 3] = __uint_as_float(f2tf32(rb0.w));
        Bs[sm][sk + 4] = __uint_as_float(f2tf32(rb1.x));
        Bs[sm][sk + 5] = __uint_as_float(f2tf32(rb1.y));
        Bs[sm][sk + 6] = __uint_as_float(f2tf32(rb1.z));
        Bs[sm][sk + 7] = __uint_as_float(f2tf32(rb1.w));
        __syncthreads();

        // prefetch next chunk
        if (c + 1 < nCh) {
            const float* An = Ag + (size_t)(c + 1) * 16;
            const float* Bn = Bg + (size_t)(c + 1) * 16;
            ra0 = aV ? *(const float4*)(An)     : z4;
            ra1 = aV ? *(const float4*)(An + 4) : z4;
            rb0 = bV ? *(const float4*)(Bn)     : z4;
            rb1 = bV ? *(const float4*)(Bn + 4) : z4;
        }

        // compute 16-deep K slab: two k=8 steps
#pragma unroll
        for (int ks = 0; ks < 16; ks += 8) {
            uint32_t a[2][4];
#pragma unroll
            for (int mi = 0; mi < 2; mi++) {
                int m = wm * 32 + mi * 16 + g;
                a[mi][0] = __float_as_uint(As[m][ks + tig]);
                a[mi][1] = __float_as_uint(As[m + 8][ks + tig]);
                a[mi][2] = __float_as_uint(As[m][ks + tig + 4]);
                a[mi][3] = __float_as_uint(As[m + 8][ks + tig + 4]);
            }
            uint32_t b[8][2];
#pragma unroll
            for (int ni = 0; ni < 8; ni++) {
                int n = wn * 64 + ni * 8 + g;
                b[ni][0] = __float_as_uint(Bs[n][ks + tig]);
                b[ni][1] = __float_as_uint(Bs[n][ks + tig + 4]);
            }
#pragma unroll
            for (int mi = 0; mi < 2; mi++)
#pragma unroll
                for (int ni = 0; ni < 8; ni++)
                    mma1688(acc[mi][ni], a[mi], b[ni]);
        }
        __syncthreads();
    }

    // epilogue: bias + optional leaky, scalar stores (N=249 misaligns float2)
#pragma unroll
    for (int mi = 0; mi < 2; mi++) {
        int r0 = row0 + wm * 32 + mi * 16 + g;
        int r1 = r0 + 8;
#pragma unroll
        for (int ni = 0; ni < 8; ni++) {
            int cc = col0 + wn * 64 + ni * 8 + tig * 2;
            float b0 = (cc < N)     ? bias[cc]     : 0.f;
            float b1 = (cc + 1 < N) ? bias[cc + 1] : 0.f;
            float v0 = acc[mi][ni][0] + b0;
            float v1 = acc[mi][ni][1] + b1;
            float v2 = acc[mi][ni][2] + b0;
            float v3 = acc[mi][ni][3] + b1;
            if (doRelu) { v0 = leaky(v0); v1 = leaky(v1); v2 = leaky(v2); v3 = leaky(v3); }
            if (r0 < M) {
                if (cc < N)     C[(size_t)r0 * N + cc]     = v0;
                if (cc + 1 < N) C[(size_t)r0 * N + cc + 1] = v1;
            }
            if (r1 < M) {
                if (cc < N)     C[(size_t)r1 * N + cc]     = v2;
                if (cc + 1 < N) C[(size_t)r1 * N + cc + 1] = v3;
            }
        }
    }
}

// ---------------------------------------------------------------------------
// einsum + antisymmetric scatter
// ---------------------------------------------------------------------------
__global__ __launch_bounds__(256) void k_einsum_scatter(int EF) {
    int tid = threadIdx.x;
    int warp = tid >> 5, lane = tid & 31;
    int s = blockIdx.x * 8 + warp;
    if (s >= EF) return;

    const float* wr = g_w     + (size_t)s * MSG;
    const float* pr = g_prods + (size_t)s * PPRODS;
    float r0 = 0.f, r1 = 0.f, r2 = 0.f;
    for (int p = lane; p < PPRODS; p += 32) {
        float pv = pr[p];
        r0 += wr[p] * pv;
        r1 += wr[PPRODS + p] * pv;
        r2 += wr[2 * PPRODS + p] * pv;
    }
#pragma unroll
    for (int off = 16; off > 0; off >>= 1) {
        r0 += __shfl_down_sync(0xffffffffu, r0, off);
        r1 += __shfl_down_sync(0xffffffffu, r1, off);
        r2 += __shfl_down_sync(0xffffffffu, r2, off);
    }
    if (lane == 0) {
        int d = g_fwd_dst[s], sn = g_fwd_src[s];
        atomicAdd(&g_agg[d * 3 + 0],  r0);
        atomicAdd(&g_agg[d * 3 + 1],  r1);
        atomicAdd(&g_agg[d * 3 + 2],  r2);
        atomicAdd(&g_agg[sn * 3 + 0], -r0);
        atomicAdd(&g_agg[sn * 3 + 1], -r1);
        atomicAdd(&g_agg[sn * 3 + 2], -r2);
    }
}

// ---------------------------------------------------------------------------
// node update: LN + MLP 19->18->17->16
// ---------------------------------------------------------------------------
__global__ __launch_bounds__(128) void k_update(
    const float* __restrict__ x,
    const float* __restrict__ ln_g, const float* __restrict__ ln_b,
    const float* __restrict__ uW1, const float* __restrict__ ub1,
    const float* __restrict__ uW2, const float* __restrict__ ub2,
    const float* __restrict__ uW3, const float* __restrict__ ub3,
    float* __restrict__ out, int N)
{
    int n = blockIdx.x * blockDim.x + threadIdx.x;
    if (n >= N) return;

    float h[19];
#pragma unroll
    for (int i = 0; i < 16; i++) h[i] = x[n * 16 + i];
#pragma unroll
    for (int k = 0; k < 3; k++) h[16 + k] = g_agg[n * 3 + k];

    float mu = 0.f;
#pragma unroll
    for (int i = 0; i < 19; i++) mu += h[i];
    mu *= (1.f / 19.f);
    float var = 0.f;
#pragma unroll
    for (int i = 0; i < 19; i++) { float d = h[i] - mu; var += d * d; }
    var *= (1.f / 19.f);
    float rstd = rsqrtf(var + 1e-5f);

    float hn[19];
#pragma unroll
    for (int i = 0; i < 19; i++) hn[i] = (h[i] - mu) * rstd * ln_g[i] + ln_b[i];

    float t1[18];
#pragma unroll
    for (int o = 0; o < 18; o++) {
        float acc = ub1[o];
#pragma unroll
        for (int i = 0; i < 19; i++) acc += hn[i] * uW1[i * 18 + o];
        t1[o] = leaky(acc);
    }
    float t2[17];
#pragma unroll
    for (int o = 0; o < 17; o++) {
        float acc = ub2[o];
#pragma unroll
        for (int i = 0; i < 18; i++) acc += t1[i] * uW2[i * 17 + o];
        t2[o] = leaky(acc);
    }
#pragma unroll
    for (int o = 0; o < 16; o++) {
        float acc = ub3[o];
#pragma unroll
        for (int i = 0; i < 17; i++) acc += t2[i] * uW3[i * 16 + o];
        out[n * 16 + o] = acc;
    }
}

// ---------------------------------------------------------------------------
// launch
// ---------------------------------------------------------------------------
extern "C" void kernel_launch(void* const* d_in, const int* in_sizes, int n_in,
                              void* d_out, int out_size)
{
    const float* x    = (const float*)d_in[0];
    const float* ea   = (const float*)d_in[1];
    const float* mW1  = (const float*)d_in[2];
    const float* mb1  = (const float*)d_in[3];
    const float* mW2  = (const float*)d_in[4];
    const float* mb2  = (const float*)d_in[5];
    const float* mW3  = (const float*)d_in[6];
    const float* mb3  = (const float*)d_in[7];
    const float* ln_g = (const float*)d_in[8];
    const float* ln_b = (const float*)d_in[9];
    const float* uW1  = (const float*)d_in[10];
    const float* ub1  = (const float*)d_in[11];
    const float* uW2  = (const float*)d_in[12];
    const float* ub2  = (const float*)d_in[13];
    const float* uW3  = (const float*)d_in[14];
    const float* ub3  = (const float*)d_in[15];
    const int*   ei   = (const int*)d_in[16];
    float* out = (float*)d_out;

    const int N  = in_sizes[0] / 16;
    const int E  = in_sizes[1] / 6;
    int EF = E / 2;
    if (EF > EF_MAX) EF = EF_MAX;

    const int* src = ei;
    const int* dst = ei + E;

    float *p_h1, *p_h2, *p_w, *p_w2t, *p_w3t;
    cudaGetSymbolAddress((void**)&p_h1,  g_h1);
    cudaGetSymbolAddress((void**)&p_h2,  g_h2);
    cudaGetSymbolAddress((void**)&p_w,   g_w);
    cudaGetSymbolAddress((void**)&p_w2t, g_w2t);
    cudaGetSymbolAddress((void**)&p_w3t, g_w3t);

    {
        int n = N * 3;
        k_zero<<<(n + 255) / 256, 256>>>(n);
    }
    k_compact<<<(E + 255) / 256, 256>>>(src, dst, E);

    {
        dim3 blk(32, 8);
        k_transpose<<<dim3(HID / 32, HID / 32), blk>>>(mW2, p_w2t, HID, HID, HID);
        k_transpose<<<dim3((MSG + 31) / 32, HID / 32), blk>>>(mW3, p_w3t, HID, MSG, HID);
    }

    k_h1_prods<<<(EF + 7) / 8, 256>>>(ea, mW1, mb1, EF);

    int Mtiles = (EF + 127) / 128;
    // GEMM2: h2 = leaky(h1 @ W2 + b2)   [EF,768]x[768,768]
    gemm_mma<<<dim3(HID / 128, Mtiles), 256>>>(p_h1, p_w2t, mb2, p_h2, EF, HID, HID, 1);
    // GEMM3: w = h2 @ W3 + b3           [EF,768]x[768,249]
    gemm_mma<<<dim3((MSG + 127) / 128, Mtiles), 256>>>(p_h2, p_w3t, mb3, p_w, EF, MSG, HID, 0);

    k_einsum_scatter<<<(EF + 7) / 8, 256>>>(EF);
    k_update<<<(N + 127) / 128, 128>>>(x, ln_g, ln_b, uW1, ub1, uW2, ub2, uW3, ub3, out, N);
}

// round 4
// speedup vs baseline: 2.3781x; 1.0481x over previous
#include <cuda_runtime.h>
#include <cuda_bf16.h>
#include <cstdint>

// ---------------------------------------------------------------------------
// Problem constants
// ---------------------------------------------------------------------------
#define NNODES_MAX 8192
#define E_MAX      131072
#define EF_MAX     (E_MAX / 2)
#define HID        768
#define PPRODS     83
#define MSG        249
#define NDIM       3

// ---------------------------------------------------------------------------
// Scratch (static __device__ BSS)
// ---------------------------------------------------------------------------
__device__ float g_h1[(size_t)EF_MAX * HID];
__device__ float g_h2[(size_t)EF_MAX * HID];
__device__ float g_w [(size_t)EF_MAX * MSG];
__device__ float g_prods[(size_t)EF_MAX * PPRODS];
__device__ float g_agg[NNODES_MAX * NDIM];
__device__ float g_w2t[HID * HID];      // mW2^T  [N=768][K=768]  (tf32-rounded)
__device__ float g_w3t[MSG * HID];      // mW3^T  [N=249][K=768]  (tf32-rounded)
__device__ int   g_fwd_e[EF_MAX];
__device__ int   g_fwd_src[EF_MAX];
__device__ int   g_fwd_dst[EF_MAX];
__device__ int   g_cnt;

__device__ __forceinline__ float leaky(float v) { return v > 0.f ? v : 0.01f * v; }

__device__ __forceinline__ float f2tf32f(float x) {
    uint32_t r;
    asm("cvt.rna.tf32.f32 %0, %1;" : "=r"(r) : "f"(x));
    return __uint_as_float(r);
}

// ---------------------------------------------------------------------------
// Small kernels
// ---------------------------------------------------------------------------
__global__ void k_zero(int nAgg) {
    int i = blockIdx.x * blockDim.x + threadIdx.x;
    if (i < nAgg) g_agg[i] = 0.f;
    if (i == 0) g_cnt = 0;
}

__global__ void k_compact(const int* __restrict__ src, const int* __restrict__ dst, int E) {
    int e = blockIdx.x * blockDim.x + threadIdx.x;
    if (e >= E) return;
    int s = src[e], d = dst[e];
    if (s < d) {
        int i = atomicAdd(&g_cnt, 1);
        if (i < EF_MAX) { g_fwd_e[i] = e; g_fwd_src[i] = s; g_fwd_dst[i] = d; }
    }
}

// h1 = tf32(leaky(edge_attr @ W1 + b1)); poly products
__global__ __launch_bounds__(256) void k_h1_prods(
    const float* __restrict__ edge_attr,
    const float* __restrict__ W1, const float* __restrict__ b1, int EF)
{
    __shared__ float sW1[6 * HID];
    __shared__ float sb1[HID];
    int tid = threadIdx.x;
    for (int i = tid; i < 6 * HID; i += blockDim.x) sW1[i] = W1[i];
    for (int i = tid; i < HID;     i += blockDim.x) sb1[i] = b1[i];
    __syncthreads();

    int warp = tid >> 5, lane = tid & 31;
    int s = blockIdx.x * 8 + warp;
    if (s >= EF) return;
    int e = g_fwd_e[s];

    float a[6];
#pragma unroll
    for (int i = 0; i < 6; i++) a[i] = edge_attr[e * 6 + i];

    float* h1r = g_h1 + (size_t)s * HID;
    for (int j = lane; j < HID; j += 32) {
        float acc = sb1[j];
#pragma unroll
        for (int i = 0; i < 6; i++) acc += a[i] * sW1[i * HID + j];
        h1r[j] = f2tf32f(leaky(acc));
    }

    if (lane == 0) {
        float* pp = g_prods + (size_t)s * PPRODS;
        int p = 0;
#pragma unroll
        for (int i = 0; i < 6; i++) pp[p++] = a[i];
#pragma unroll
        for (int i = 0; i < 6; i++)
            for (int j = i; j < 6; j++) pp[p++] = a[i] * a[j];
#pragma unroll
        for (int i = 0; i < 6; i++)
            for (int j = i; j < 6; j++)
                for (int k = j; k < 6; k++) pp[p++] = a[i] * a[j] * a[k];
    }
}

// tiled transpose + tf32 round: Wt[n*K_ld + k] = tf32(W[k*N + n])
__global__ void k_transpose(const float* __restrict__ W, float* __restrict__ Wt,
                            int K, int N, int K_ld)
{
    __shared__ float t[32][33];
    int kb = blockIdx.y * 32, nb = blockIdx.x * 32;
    int tx = threadIdx.x, ty = threadIdx.y;
    for (int i = ty; i < 32; i += 8) {
        int k = kb + i, n = nb + tx;
        t[i][tx] = (k < K && n < N) ? W[(size_t)k * N + n] : 0.f;
    }
    __syncthreads();
    for (int i = ty; i < 32; i += 8) {
        int n = nb + i, k = kb + tx;
        if (n < N && k < K) Wt[(size_t)n * K_ld + k] = f2tf32f(t[tx][i]);
    }
}

// ---------------------------------------------------------------------------
// tf32 mma.sync GEMM, fragment-permuted smem, double-buffered, 1 sync/chunk.
// C[M,N] = act(A[M,K] @ Bt[N,K]^T + bias). BM=BN=128, BK=16.
// 8 warps: wm=wid&3 (M), wn=wid>>2 (N); warp tile 32x64, m16n8k8.
// Inputs A, Bt must already be tf32-rounded.
// ---------------------------------------------------------------------------
#define A_SLAB 1032       // floats; skewed slab stride (banks of slab1 shifted by 8)
#define A_BUFP 2064       // per-buffer stride (16B aligned)
#define B_SLAB 1028       // skew by 4 words
#define B_BUFP 2056

__device__ __forceinline__ void mma1688(float* c, const uint32_t* a, const uint32_t* b) {
    asm volatile(
        "mma.sync.aligned.m16n8k8.row.col.f32.tf32.tf32.f32 "
        "{%0,%1,%2,%3}, {%4,%5,%6,%7}, {%8,%9}, {%0,%1,%2,%3};"
        : "+f"(c[0]), "+f"(c[1]), "+f"(c[2]), "+f"(c[3])
        : "r"(a[0]), "r"(a[1]), "r"(a[2]), "r"(a[3]), "r"(b[0]), "r"(b[1]));
}

__global__ __launch_bounds__(256, 2) void gemm_mma(
    const float* __restrict__ A, const float* __restrict__ Bt,
    const float* __restrict__ bias, float* __restrict__ C,
    int M, int N, int K, int doRelu, int roundOut)
{
    __shared__ __align__(16) float As[2 * A_BUFP];
    __shared__ __align__(16) float Bs[2 * B_BUFP];

    const int tid  = threadIdx.x;
    const int wid  = tid >> 5;
    const int lane = tid & 31;
    const int g    = lane >> 2;
    const int tig  = lane & 3;
    const int wm   = wid & 3;
    const int wn   = wid >> 2;
    const int row0 = blockIdx.y * 128;
    const int col0 = blockIdx.x * 128;

    // staging identity: thread handles row sm, k-slab s (8 floats each of A and B)
    const int sm = tid >> 1;
    const int s  = tid & 1;
    const bool aV = (row0 + sm) < M;
    const bool bV = (col0 + sm) < N;
    const float* Ag = A  + (size_t)(row0 + sm) * K + s * 8;
    const float* Bg = Bt + (size_t)(col0 + sm) * K + s * 8;

    // permuted-store bases (float offsets within one buffer)
    //   A dest: s*A_SLAB + (sm>>4)*128 + ((sm&7)*4 + j)*4 + ((sm>>3)&1)*2   (float2 per j)
    //   B dest: s*B_SLAB + (sm>>3)*64  + (sm&7)*8 + j*2                     (float2 per j)
    float* Ad0 = As + s * A_SLAB + (sm >> 4) * 128 + (sm & 7) * 16 + ((sm >> 3) & 1) * 2;
    float* Bd0 = Bs + s * B_SLAB + (sm >> 3) * 64 + (sm & 7) * 8;

    float acc[2][8][4];
#pragma unroll
    for (int mi = 0; mi < 2; mi++)
#pragma unroll
        for (int ni = 0; ni < 8; ni++)
#pragma unroll
            for (int q = 0; q < 4; q++) acc[mi][ni][q] = 0.f;

    const int nCh = K / 16;
    const float4 z4 = make_float4(0.f, 0.f, 0.f, 0.f);
    float4 ra0, ra1, rb0, rb1;

    ra0 = aV ? *(const float4*)(Ag)     : z4;
    ra1 = aV ? *(const float4*)(Ag + 4) : z4;
    rb0 = bV ? *(const float4*)(Bg)     : z4;
    rb1 = bV ? *(const float4*)(Bg + 4) : z4;

    for (int c = 0; c < nCh; ++c) {
        const int buf = c & 1;
        // stage current regs into buf (pairs (k, k+4))
        {
            float* Ad = Ad0 + buf * A_BUFP;
            float* Bd = Bd0 + buf * B_BUFP;
            *(float2*)(Ad +  0) = make_float2(ra0.x, ra1.x);
            *(float2*)(Ad +  4) = make_float2(ra0.y, ra1.y);
            *(float2*)(Ad +  8) = make_float2(ra0.z, ra1.z);
            *(float2*)(Ad + 12) = make_float2(ra0.w, ra1.w);
            *(float2*)(Bd +  0) = make_float2(rb0.x, rb1.x);
            *(float2*)(Bd +  2) = make_float2(rb0.y, rb1.y);
            *(float2*)(Bd +  4) = make_float2(rb0.z, rb1.z);
            *(float2*)(Bd +  6) = make_float2(rb0.w, rb1.w);
        }
        // prefetch next chunk
        if (c + 1 < nCh) {
            const float* An = Ag + (size_t)(c + 1) * 16;
            const float* Bn = Bg + (size_t)(c + 1) * 16;
            ra0 = aV ? *(const float4*)(An)     : z4;
            ra1 = aV ? *(const float4*)(An + 4) : z4;
            rb0 = bV ? *(const float4*)(Bn)     : z4;
            rb1 = bV ? *(const float4*)(Bn + 4) : z4;
        }
        __syncthreads();

        // compute chunk from buf: 2 k-slabs
        const float* Ab = As + buf * A_BUFP;
        const float* Bb = Bs + buf * B_BUFP;
#pragma unroll
        for (int ks = 0; ks < 2; ks++) {
            uint32_t a[2][4];
#pragma unroll
            for (int mi = 0; mi < 2; mi++) {
                float4 v = *(const float4*)(Ab + ks * A_SLAB + (wm * 2 + mi) * 128 + lane * 4);
                // stored order: [A[g][tig], A[g][tig+4], A[g+8][tig], A[g+8][tig+4]]
                a[mi][0] = __float_as_uint(v.x);
                a[mi][1] = __float_as_uint(v.z);
                a[mi][2] = __float_as_uint(v.y);
                a[mi][3] = __float_as_uint(v.w);
            }
            uint32_t b[8][2];
#pragma unroll
            for (int ni = 0; ni < 8; ni++) {
                float2 v = *(const float2*)(Bb + ks * B_SLAB + (wn * 8 + ni) * 64 + lane * 2);
                b[ni][0] = __float_as_uint(v.x);
                b[ni][1] = __float_as_uint(v.y);
            }
#pragma unroll
            for (int mi = 0; mi < 2; mi++)
#pragma unroll
                for (int ni = 0; ni < 8; ni++)
                    mma1688(acc[mi][ni], a[mi], b[ni]);
        }
        __syncthreads();
    }

    // epilogue
    const bool nEven = (N & 1) == 0;
#pragma unroll
    for (int mi = 0; mi < 2; mi++) {
        int r0 = row0 + wm * 32 + mi * 16 + g;
        int r1 = r0 + 8;
#pragma unroll
        for (int ni = 0; ni < 8; ni++) {
            int cc = col0 + wn * 64 + ni * 8 + tig * 2;
            float b0 = (cc < N)     ? bias[cc]     : 0.f;
            float b1 = (cc + 1 < N) ? bias[cc + 1] : 0.f;
            float v0 = acc[mi][ni][0] + b0;
            float v1 = acc[mi][ni][1] + b1;
            float v2 = acc[mi][ni][2] + b0;
            float v3 = acc[mi][ni][3] + b1;
            if (doRelu) { v0 = leaky(v0); v1 = leaky(v1); v2 = leaky(v2); v3 = leaky(v3); }
            if (roundOut) {
                v0 = f2tf32f(v0); v1 = f2tf32f(v1); v2 = f2tf32f(v2); v3 = f2tf32f(v3);
            }
            if (nEven && cc + 1 < N) {
                if (r0 < M) *(float2*)(C + (size_t)r0 * N + cc) = make_float2(v0, v1);
                if (r1 < M) *(float2*)(C + (size_t)r1 * N + cc) = make_float2(v2, v3);
            } else {
                if (r0 < M) {
                    if (cc < N)     C[(size_t)r0 * N + cc]     = v0;
                    if (cc + 1 < N) C[(size_t)r0 * N + cc + 1] = v1;
                }
                if (r1 < M) {
                    if (cc < N)     C[(size_t)r1 * N + cc]     = v2;
                    if (cc + 1 < N) C[(size_t)r1 * N + cc + 1] = v3;
                }
            }
        }
    }
}

// ---------------------------------------------------------------------------
// einsum + antisymmetric scatter
// ---------------------------------------------------------------------------
__global__ __launch_bounds__(256) void k_einsum_scatter(int EF) {
    int tid = threadIdx.x;
    int warp = tid >> 5, lane = tid & 31;
    int s = blockIdx.x * 8 + warp;
    if (s >= EF) return;

    const float* wr = g_w     + (size_t)s * MSG;
    const float* pr = g_prods + (size_t)s * PPRODS;
    float r0 = 0.f, r1 = 0.f, r2 = 0.f;
    for (int p = lane; p < PPRODS; p += 32) {
        float pv = pr[p];
        r0 += wr[p] * pv;
        r1 += wr[PPRODS + p] * pv;
        r2 += wr[2 * PPRODS + p] * pv;
    }
#pragma unroll
    for (int off = 16; off > 0; off >>= 1) {
        r0 += __shfl_down_sync(0xffffffffu, r0, off);
        r1 += __shfl_down_sync(0xffffffffu, r1, off);
        r2 += __shfl_down_sync(0xffffffffu, r2, off);
    }
    if (lane == 0) {
        int d = g_fwd_dst[s], sn = g_fwd_src[s];
        atomicAdd(&g_agg[d * 3 + 0],  r0);
        atomicAdd(&g_agg[d * 3 + 1],  r1);
        atomicAdd(&g_agg[d * 3 + 2],  r2);
        atomicAdd(&g_agg[sn * 3 + 0], -r0);
        atomicAdd(&g_agg[sn * 3 + 1], -r1);
        atomicAdd(&g_agg[sn * 3 + 2], -r2);
    }
}

// ---------------------------------------------------------------------------
// node update: LN + MLP 19->18->17->16
// ---------------------------------------------------------------------------
__global__ __launch_bounds__(128) void k_update(
    const float* __restrict__ x,
    const float* __restrict__ ln_g, const float* __restrict__ ln_b,
    const float* __restrict__ uW1, const float* __restrict__ ub1,
    const float* __restrict__ uW2, const float* __restrict__ ub2,
    const float* __restrict__ uW3, const float* __restrict__ ub3,
    float* __restrict__ out, int N)
{
    int n = blockIdx.x * blockDim.x + threadIdx.x;
    if (n >= N) return;

    float h[19];
#pragma unroll
    for (int i = 0; i < 16; i++) h[i] = x[n * 16 + i];
#pragma unroll
    for (int k = 0; k < 3; k++) h[16 + k] = g_agg[n * 3 + k];

    float mu = 0.f;
#pragma unroll
    for (int i = 0; i < 19; i++) mu += h[i];
    mu *= (1.f / 19.f);
    float var = 0.f;
#pragma unroll
    for (int i = 0; i < 19; i++) { float d = h[i] - mu; var += d * d; }
    var *= (1.f / 19.f);
    float rstd = rsqrtf(var + 1e-5f);

    float hn[19];
#pragma unroll
    for (int i = 0; i < 19; i++) hn[i] = (h[i] - mu) * rstd * ln_g[i] + ln_b[i];

    float t1[18];
#pragma unroll
    for (int o = 0; o < 18; o++) {
        float acc = ub1[o];
#pragma unroll
        for (int i = 0; i < 19; i++) acc += hn[i] * uW1[i * 18 + o];
        t1[o] = leaky(acc);
    }
    float t2[17];
#pragma unroll
    for (int o = 0; o < 17; o++) {
        float acc = ub2[o];
#pragma unroll
        for (int i = 0; i < 18; i++) acc += t1[i] * uW2[i * 17 + o];
        t2[o] = leaky(acc);
    }
#pragma unroll
    for (int o = 0; o < 16; o++) {
        float acc = ub3[o];
#pragma unroll
        for (int i = 0; i < 17; i++) acc += t2[i] * uW3[i * 16 + o];
        out[n * 16 + o] = acc;
    }
}

// ---------------------------------------------------------------------------
// launch
// ---------------------------------------------------------------------------
extern "C" void kernel_launch(void* const* d_in, const int* in_sizes, int n_in,
                              void* d_out, int out_size)
{
    const float* x    = (const float*)d_in[0];
    const float* ea   = (const float*)d_in[1];
    const float* mW1  = (const float*)d_in[2];
    const float* mb1  = (const float*)d_in[3];
    const float* mW2  = (const float*)d_in[4];
    const float* mb2  = (const float*)d_in[5];
    const float* mW3  = (const float*)d_in[6];
    const float* mb3  = (const float*)d_in[7];
    const float* ln_g = (const float*)d_in[8];
    const float* ln_b = (const float*)d_in[9];
    const float* uW1  = (const float*)d_in[10];
    const float* ub1  = (const float*)d_in[11];
    const float* uW2  = (const float*)d_in[12];
    const float* ub2  = (const float*)d_in[13];
    const float* uW3  = (const float*)d_in[14];
    const float* ub3  = (const float*)d_in[15];
    const int*   ei   = (const int*)d_in[16];
    float* out = (float*)d_out;

    const int N  = in_sizes[0] / 16;
    const int E  = in_sizes[1] / 6;
    int EF = E / 2;
    if (EF > EF_MAX) EF = EF_MAX;

    const int* src = ei;
    const int* dst = ei + E;

    float *p_h1, *p_h2, *p_w, *p_w2t, *p_w3t;
    cudaGetSymbolAddress((void**)&p_h1,  g_h1);
    cudaGetSymbolAddress((void**)&p_h2,  g_h2);
    cudaGetSymbolAddress((void**)&p_w,   g_w);
    cudaGetSymbolAddress((void**)&p_w2t, g_w2t);
    cudaGetSymbolAddress((void**)&p_w3t, g_w3t);

    {
        int n = N * 3;
        k_zero<<<(n + 255) / 256, 256>>>(n);
    }
    k_compact<<<(E + 255) / 256, 256>>>(src, dst, E);

    {
        dim3 blk(32, 8);
        k_transpose<<<dim3(HID / 32, HID / 32), blk>>>(mW2, p_w2t, HID, HID, HID);
        k_transpose<<<dim3((MSG + 31) / 32, HID / 32), blk>>>(mW3, p_w3t, HID, MSG, HID);
    }

    k_h1_prods<<<(EF + 7) / 8, 256>>>(ea, mW1, mb1, EF);

    int Mtiles = (EF + 127) / 128;
    // GEMM2: h2 = tf32(leaky(h1 @ W2 + b2))   [EF,768]x[768,768]
    gemm_mma<<<dim3(HID / 128, Mtiles), 256>>>(p_h1, p_w2t, mb2, p_h2, EF, HID, HID, 1, 1);
    // GEMM3: w = h2 @ W3 + b3                 [EF,768]x[768,249]
    gemm_mma<<<dim3((MSG + 127) / 128, Mtiles), 256>>>(p_h2, p_w3t, mb3, p_w, EF, MSG, HID, 0, 0);

    k_einsum_scatter<<<(EF + 7) / 8, 256>>>(EF);
    k_update<<<(N + 127) / 128, 128>>>(x, ln_g, ln_b, uW1, ub1, uW2, ub2, uW3, ub3, out, N);
}

// round 5
// speedup vs baseline: 5.1400x; 2.1614x over previous
#include <cuda_runtime.h>
#include <cuda_fp16.h>
#include <cstdint>

// ---------------------------------------------------------------------------
// Problem constants
// ---------------------------------------------------------------------------
#define NNODES_MAX 8192
#define E_MAX      131072
#define EF_MAX     (E_MAX / 2)
#define HID        768
#define PPRODS     83
#define MSG        249
#define NDIM       3

// ---------------------------------------------------------------------------
// Scratch (static __device__ BSS)
// ---------------------------------------------------------------------------
__device__ __half g_h1h[(size_t)EF_MAX * HID];   // 96 MB, fp16
__device__ __half g_h2h[(size_t)EF_MAX * HID];   // 96 MB, fp16
__device__ float  g_w  [(size_t)EF_MAX * MSG];   // 64 MB
__device__ float  g_prods[(size_t)EF_MAX * PPRODS];
__device__ float  g_agg[NNODES_MAX * NDIM];
__device__ __half g_w2t[HID * HID];              // mW2^T [768][768] fp16
__device__ __half g_w3t[MSG * HID];              // mW3^T [249][768] fp16
__device__ int    g_fwd_e[EF_MAX];
__device__ int    g_fwd_src[EF_MAX];
__device__ int    g_fwd_dst[EF_MAX];
__device__ int    g_cnt;

__device__ __forceinline__ float leaky(float v) { return v > 0.f ? v : 0.01f * v; }

__device__ __forceinline__ uint32_t smem_u32(const void* p) {
    uint32_t a;
    asm("{ .reg .u64 t; cvta.to.shared.u64 t, %1; cvt.u32.u64 %0, t; }" : "=r"(a) : "l"(p));
    return a;
}

__device__ __forceinline__ void cpa16(uint32_t dst, const void* src, int valid) {
    int sz = valid ? 16 : 0;
    asm volatile("cp.async.cg.shared.global [%0], [%1], 16, %2;"
                 :: "r"(dst), "l"(src), "r"(sz));
}
__device__ __forceinline__ void cpa_commit() {
    asm volatile("cp.async.commit_group;" ::: "memory");
}
__device__ __forceinline__ void cpa_wait1() {
    asm volatile("cp.async.wait_group 1;" ::: "memory");
}

__device__ __forceinline__ void ldm_x4(uint32_t addr, uint32_t* r) {
    asm volatile("ldmatrix.sync.aligned.m8n8.x4.shared.b16 {%0,%1,%2,%3}, [%4];"
                 : "=r"(r[0]), "=r"(r[1]), "=r"(r[2]), "=r"(r[3]) : "r"(addr));
}

__device__ __forceinline__ void mma16816(float* c, const uint32_t* a, const uint32_t* b) {
    asm volatile(
        "mma.sync.aligned.m16n8k16.row.col.f32.f16.f16.f32 "
        "{%0,%1,%2,%3}, {%4,%5,%6,%7}, {%8,%9}, {%0,%1,%2,%3};"
        : "+f"(c[0]), "+f"(c[1]), "+f"(c[2]), "+f"(c[3])
        : "r"(a[0]), "r"(a[1]), "r"(a[2]), "r"(a[3]), "r"(b[0]), "r"(b[1]));
}

// ---------------------------------------------------------------------------
// Small kernels
// ---------------------------------------------------------------------------
__global__ void k_zero(int nAgg) {
    int i = blockIdx.x * blockDim.x + threadIdx.x;
    if (i < nAgg) g_agg[i] = 0.f;
    if (i == 0) g_cnt = 0;
}

__global__ void k_compact(const int* __restrict__ src, const int* __restrict__ dst, int E) {
    int e = blockIdx.x * blockDim.x + threadIdx.x;
    if (e >= E) return;
    int s = src[e], d = dst[e];
    if (s < d) {
        int i = atomicAdd(&g_cnt, 1);
        if (i < EF_MAX) { g_fwd_e[i] = e; g_fwd_src[i] = s; g_fwd_dst[i] = d; }
    }
}

// h1 = fp16(leaky(edge_attr @ W1 + b1)); poly products
__global__ __launch_bounds__(256) void k_h1_prods(
    const float* __restrict__ edge_attr,
    const float* __restrict__ W1, const float* __restrict__ b1, int EF)
{
    __shared__ float sW1[6 * HID];
    __shared__ float sb1[HID];
    int tid = threadIdx.x;
    for (int i = tid; i < 6 * HID; i += blockDim.x) sW1[i] = W1[i];
    for (int i = tid; i < HID;     i += blockDim.x) sb1[i] = b1[i];
    __syncthreads();

    int warp = tid >> 5, lane = tid & 31;
    int s = blockIdx.x * 8 + warp;
    if (s >= EF) return;
    int e = g_fwd_e[s];

    float a[6];
#pragma unroll
    for (int i = 0; i < 6; i++) a[i] = edge_attr[e * 6 + i];

    __half* h1r = g_h1h + (size_t)s * HID;
    for (int j = lane; j < HID; j += 32) {
        float acc = sb1[j];
#pragma unroll
        for (int i = 0; i < 6; i++) acc += a[i] * sW1[i * HID + j];
        h1r[j] = __float2half(leaky(acc));
    }

    if (lane == 0) {
        float* pp = g_prods + (size_t)s * PPRODS;
        int p = 0;
#pragma unroll
        for (int i = 0; i < 6; i++) pp[p++] = a[i];
#pragma unroll
        for (int i = 0; i < 6; i++)
            for (int j = i; j < 6; j++) pp[p++] = a[i] * a[j];
#pragma unroll
        for (int i = 0; i < 6; i++)
            for (int j = i; j < 6; j++)
                for (int k = j; k < 6; k++) pp[p++] = a[i] * a[j] * a[k];
    }
}

// tiled transpose + fp16 round: Wt[n*K_ld + k] = fp16(W[k*N + n])
__global__ void k_transpose(const float* __restrict__ W, __half* __restrict__ Wt,
                            int K, int N, int K_ld)
{
    __shared__ float t[32][33];
    int kb = blockIdx.y * 32, nb = blockIdx.x * 32;
    int tx = threadIdx.x, ty = threadIdx.y;
    for (int i = ty; i < 32; i += 8) {
        int k = kb + i, n = nb + tx;
        t[i][tx] = (k < K && n < N) ? W[(size_t)k * N + n] : 0.f;
    }
    __syncthreads();
    for (int i = ty; i < 32; i += 8) {
        int n = nb + i, k = kb + tx;
        if (n < N && k < K) Wt[(size_t)n * K_ld + k] = __float2half(t[tx][i]);
    }
}

// ---------------------------------------------------------------------------
// fp16 mma GEMM: C[M,N] = act(A[M,K] @ Bt[N,K]^T + bias)
// BM=BN=128, BK=32, 3-stage cp.async, ldmatrix fragments, m16n8k16 f32 accum.
// 8 warps: wm=wid&3 (M), wn=wid>>2 (N); warp tile 32x64.
// A, Bt are fp16 (pre-rounded); bias f32; out f32 or fp16 per outHalf.
// ---------------------------------------------------------------------------
#define AROW   40                 // halves per smem row (32 data + 8 pad)
#define STG_H  (128 * AROW)       // halves per stage per operand (5120)
#define NSTAGE 3
#define GEMM_SMEM_BYTES (NSTAGE * STG_H * 2 * 2)   // 61440

__global__ __launch_bounds__(256, 2) void gemm_fp16(
    const __half* __restrict__ A, const __half* __restrict__ Bt,
    const float* __restrict__ bias, void* __restrict__ Cout,
    int M, int N, int K, int doRelu, int outHalf)
{
    extern __shared__ __align__(16) __half smh[];
    __half* As = smh;
    __half* Bs = smh + NSTAGE * STG_H;

    const int tid  = threadIdx.x;
    const int wid  = tid >> 5;
    const int lane = tid & 31;
    const int g    = lane >> 2;
    const int tig  = lane & 3;
    const int wm   = wid & 3;
    const int wn   = wid >> 2;
    const int row0 = blockIdx.y * 128;
    const int col0 = blockIdx.x * 128;

    // staging: thread -> row r (0..127), k-half s (0..1), 16 halves = 32B
    const int r = tid >> 1;
    const int s = tid & 1;
    const int aV = (row0 + r) < M;
    const int bV = (col0 + r) < N;
    const __half* Ag = A  + (size_t)(row0 + r) * K + s * 16;
    const __half* Bg = Bt + (size_t)(col0 + r) * K + s * 16;

    const uint32_t aBase = smem_u32(As);
    const uint32_t bBase = smem_u32(Bs);
    const uint32_t aDst = aBase + (uint32_t)(r * AROW + s * 16) * 2;
    const uint32_t bDst = bBase + (uint32_t)(r * AROW + s * 16) * 2;

    // ldmatrix addresses (per thread, per stage offset added later)
    // A x4 for mi: rows wm*32+mi*16 + (lane&15), chunk (lane>>4) [+2*ks]
    uint32_t aLd[2];
#pragma unroll
    for (int mi = 0; mi < 2; mi++)
        aLd[mi] = aBase + (uint32_t)(((wm * 32 + mi * 16 + (lane & 15)) * AROW
                                      + (lane >> 4) * 8) * 2);
    // B x4 for np: rows wn*64+np*16 + (lane&7) + ((lane>>4)<<3), chunk ((lane>>3)&1) [+2*ks]
    uint32_t bLd[4];
#pragma unroll
    for (int np = 0; np < 4; np++)
        bLd[np] = bBase + (uint32_t)(((wn * 64 + np * 16 + (lane & 7) + ((lane >> 4) << 3)) * AROW
                                      + ((lane >> 3) & 1) * 8) * 2);

    float acc[2][8][4];
#pragma unroll
    for (int mi = 0; mi < 2; mi++)
#pragma unroll
        for (int ni = 0; ni < 8; ni++)
#pragma unroll
            for (int q = 0; q < 4; q++) acc[mi][ni][q] = 0.f;

    const int nCh = K / 32;
    const uint32_t stB = (uint32_t)STG_H * 2;   // stage stride bytes

    // prologue: stage chunks 0 and 1
#pragma unroll
    for (int c = 0; c < 2; c++) {
        uint32_t so = c * stB;
        cpa16(aDst + so,      Ag + (size_t)c * 32,     aV);
        cpa16(aDst + so + 16, Ag + (size_t)c * 32 + 8, aV);
        cpa16(bDst + so,      Bg + (size_t)c * 32,     bV);
        cpa16(bDst + so + 16, Bg + (size_t)c * 32 + 8, bV);
        cpa_commit();
    }

    for (int c = 0; c < nCh; ++c) {
        const int st = c % NSTAGE;
        cpa_wait1();
        __syncthreads();

        // issue chunk c+2 into stage (c+2)%NSTAGE
        if (c + 2 < nCh) {
            uint32_t so = ((c + 2) % NSTAGE) * stB;
            cpa16(aDst + so,      Ag + (size_t)(c + 2) * 32,     aV);
            cpa16(aDst + so + 16, Ag + (size_t)(c + 2) * 32 + 8, aV);
            cpa16(bDst + so,      Bg + (size_t)(c + 2) * 32,     bV);
            cpa16(bDst + so + 16, Bg + (size_t)(c + 2) * 32 + 8, bV);
        }
        cpa_commit();

        // compute chunk c from stage st (2 k16 steps)
        const uint32_t so = st * stB;
#pragma unroll
        for (int ks = 0; ks < 2; ks++) {
            uint32_t a[2][4];
#pragma unroll
            for (int mi = 0; mi < 2; mi++)
                ldm_x4(aLd[mi] + so + ks * 32, a[mi]);
            uint32_t b[4][4];
#pragma unroll
            for (int np = 0; np < 4; np++)
                ldm_x4(bLd[np] + so + ks * 32, b[np]);
#pragma unroll
            for (int mi = 0; mi < 2; mi++)
#pragma unroll
                for (int ni = 0; ni < 8; ni++)
                    mma16816(acc[mi][ni], a[mi], b[ni >> 1] + (ni & 1) * 2);
        }
    }

    // epilogue
    float* Cf = (float*)Cout;
    __half* Ch = (__half*)Cout;
    const bool nEven = (N & 1) == 0;
#pragma unroll
    for (int mi = 0; mi < 2; mi++) {
        int r0 = row0 + wm * 32 + mi * 16 + g;
        int r1 = r0 + 8;
#pragma unroll
        for (int ni = 0; ni < 8; ni++) {
            int cc = col0 + wn * 64 + ni * 8 + tig * 2;
            float b0 = (cc < N)     ? bias[cc]     : 0.f;
            float b1 = (cc + 1 < N) ? bias[cc + 1] : 0.f;
            float v0 = acc[mi][ni][0] + b0;
            float v1 = acc[mi][ni][1] + b1;
            float v2 = acc[mi][ni][2] + b0;
            float v3 = acc[mi][ni][3] + b1;
            if (doRelu) { v0 = leaky(v0); v1 = leaky(v1); v2 = leaky(v2); v3 = leaky(v3); }
            if (outHalf) {
                if (cc + 1 < N) {
                    if (r0 < M) *(__half2*)(Ch + (size_t)r0 * N + cc) =
                        __floats2half2_rn(v0, v1);
                    if (r1 < M) *(__half2*)(Ch + (size_t)r1 * N + cc) =
                        __floats2half2_rn(v2, v3);
                } else if (cc < N) {
                    if (r0 < M) Ch[(size_t)r0 * N + cc] = __float2half(v0);
                    if (r1 < M) Ch[(size_t)r1 * N + cc] = __float2half(v2);
                }
            } else {
                if (nEven && cc + 1 < N) {
                    if (r0 < M) *(float2*)(Cf + (size_t)r0 * N + cc) = make_float2(v0, v1);
                    if (r1 < M) *(float2*)(Cf + (size_t)r1 * N + cc) = make_float2(v2, v3);
                } else {
                    if (r0 < M) {
                        if (cc < N)     Cf[(size_t)r0 * N + cc]     = v0;
                        if (cc + 1 < N) Cf[(size_t)r0 * N + cc + 1] = v1;
                    }
                    if (r1 < M) {
                        if (cc < N)     Cf[(size_t)r1 * N + cc]     = v2;
                        if (cc + 1 < N) Cf[(size_t)r1 * N + cc + 1] = v3;
                    }
                }
            }
        }
    }
}

// ---------------------------------------------------------------------------
// einsum + antisymmetric scatter
// ---------------------------------------------------------------------------
__global__ __launch_bounds__(256) void k_einsum_scatter(int EF) {
    int tid = threadIdx.x;
    int warp = tid >> 5, lane = tid & 31;
    int s = blockIdx.x * 8 + warp;
    if (s >= EF) return;

    const float* wr = g_w     + (size_t)s * MSG;
    const float* pr = g_prods + (size_t)s * PPRODS;
    float r0 = 0.f, r1 = 0.f, r2 = 0.f;
    for (int p = lane; p < PPRODS; p += 32) {
        float pv = pr[p];
        r0 += wr[p] * pv;
        r1 += wr[PPRODS + p] * pv;
        r2 += wr[2 * PPRODS + p] * pv;
    }
#pragma unroll
    for (int off = 16; off > 0; off >>= 1) {
        r0 += __shfl_down_sync(0xffffffffu, r0, off);
        r1 += __shfl_down_sync(0xffffffffu, r1, off);
        r2 += __shfl_down_sync(0xffffffffu, r2, off);
    }
    if (lane == 0) {
        int d = g_fwd_dst[s], sn = g_fwd_src[s];
        atomicAdd(&g_agg[d * 3 + 0],  r0);
        atomicAdd(&g_agg[d * 3 + 1],  r1);
        atomicAdd(&g_agg[d * 3 + 2],  r2);
        atomicAdd(&g_agg[sn * 3 + 0], -r0);
        atomicAdd(&g_agg[sn * 3 + 1], -r1);
        atomicAdd(&g_agg[sn * 3 + 2], -r2);
    }
}

// ---------------------------------------------------------------------------
// node update: LN + MLP 19->18->17->16
// ---------------------------------------------------------------------------
__global__ __launch_bounds__(128) void k_update(
    const float* __restrict__ x,
    const float* __restrict__ ln_g, const float* __restrict__ ln_b,
    const float* __restrict__ uW1, const float* __restrict__ ub1,
    const float* __restrict__ uW2, const float* __restrict__ ub2,
    const float* __restrict__ uW3, const float* __restrict__ ub3,
    float* __restrict__ out, int N)
{
    int n = blockIdx.x * blockDim.x + threadIdx.x;
    if (n >= N) return;

    float h[19];
#pragma unroll
    for (int i = 0; i < 16; i++) h[i] = x[n * 16 + i];
#pragma unroll
    for (int k = 0; k < 3; k++) h[16 + k] = g_agg[n * 3 + k];

    float mu = 0.f;
#pragma unroll
    for (int i = 0; i < 19; i++) mu += h[i];
    mu *= (1.f / 19.f);
    float var = 0.f;
#pragma unroll
    for (int i = 0; i < 19; i++) { float d = h[i] - mu; var += d * d; }
    var *= (1.f / 19.f);
    float rstd = rsqrtf(var + 1e-5f);

    float hn[19];
#pragma unroll
    for (int i = 0; i < 19; i++) hn[i] = (h[i] - mu) * rstd * ln_g[i] + ln_b[i];

    float t1[18];
#pragma unroll
    for (int o = 0; o < 18; o++) {
        float acc = ub1[o];
#pragma unroll
        for (int i = 0; i < 19; i++) acc += hn[i] * uW1[i * 18 + o];
        t1[o] = leaky(acc);
    }
    float t2[17];
#pragma unroll
    for (int o = 0; o < 17; o++) {
        float acc = ub2[o];
#pragma unroll
        for (int i = 0; i < 18; i++) acc += t1[i] * uW2[i * 17 + o];
        t2[o] = leaky(acc);
    }
#pragma unroll
    for (int o = 0; o < 16; o++) {
        float acc = ub3[o];
#pragma unroll
        for (int i = 0; i < 17; i++) acc += t2[i] * uW3[i * 16 + o];
        out[n * 16 + o] = acc;
    }
}

// ---------------------------------------------------------------------------
// launch
// ---------------------------------------------------------------------------
extern "C" void kernel_launch(void* const* d_in, const int* in_sizes, int n_in,
                              void* d_out, int out_size)
{
    const float* x    = (const float*)d_in[0];
    const float* ea   = (const float*)d_in[1];
    const float* mW1  = (const float*)d_in[2];
    const float* mb1  = (const float*)d_in[3];
    const float* mW2  = (const float*)d_in[4];
    const float* mb2  = (const float*)d_in[5];
    const float* mW3  = (const float*)d_in[6];
    const float* mb3  = (const float*)d_in[7];
    const float* ln_g = (const float*)d_in[8];
    const float* ln_b = (const float*)d_in[9];
    const float* uW1  = (const float*)d_in[10];
    const float* ub1  = (const float*)d_in[11];
    const float* uW2  = (const float*)d_in[12];
    const float* ub2  = (const float*)d_in[13];
    const float* uW3  = (const float*)d_in[14];
    const float* ub3  = (const float*)d_in[15];
    const int*   ei   = (const int*)d_in[16];
    float* out = (float*)d_out;

    const int N  = in_sizes[0] / 16;
    const int E  = in_sizes[1] / 6;
    int EF = E / 2;
    if (EF > EF_MAX) EF = EF_MAX;

    const int* src = ei;
    const int* dst = ei + E;

    __half *p_h1, *p_h2, *p_w2t, *p_w3t;
    float  *p_w;
    cudaGetSymbolAddress((void**)&p_h1,  g_h1h);
    cudaGetSymbolAddress((void**)&p_h2,  g_h2h);
    cudaGetSymbolAddress((void**)&p_w,   g_w);
    cudaGetSymbolAddress((void**)&p_w2t, g_w2t);
    cudaGetSymbolAddress((void**)&p_w3t, g_w3t);

    cudaFuncSetAttribute(gemm_fp16, cudaFuncAttributeMaxDynamicSharedMemorySize,
                         GEMM_SMEM_BYTES);

    {
        int n = N * 3;
        k_zero<<<(n + 255) / 256, 256>>>(n);
    }
    k_compact<<<(E + 255) / 256, 256>>>(src, dst, E);

    {
        dim3 blk(32, 8);
        k_transpose<<<dim3(HID / 32, HID / 32), blk>>>(mW2, p_w2t, HID, HID, HID);
        k_transpose<<<dim3((MSG + 31) / 32, HID / 32), blk>>>(mW3, p_w3t, HID, MSG, HID);
    }

    k_h1_prods<<<(EF + 7) / 8, 256>>>(ea, mW1, mb1, EF);

    int Mtiles = (EF + 127) / 128;
    // GEMM2: h2 = fp16(leaky(h1 @ W2 + b2))   [EF,768]x[768,768]
    gemm_fp16<<<dim3(HID / 128, Mtiles), 256, GEMM_SMEM_BYTES>>>(
        p_h1, p_w2t, mb2, p_h2, EF, HID, HID, 1, 1);
    // GEMM3: w = h2 @ W3 + b3 (f32 out)       [EF,768]x[768,249]
    gemm_fp16<<<dim3((MSG + 127) / 128, Mtiles), 256, GEMM_SMEM_BYTES>>>(
        p_h2, p_w3t, mb3, p_w, EF, MSG, HID, 0, 0);

    k_einsum_scatter<<<(EF + 7) / 8, 256>>>(EF);
    k_update<<<(N + 127) / 128, 128>>>(x, ln_g, ln_b, uW1, ub1, uW2, ub2, uW3, ub3, out, N);
}

// round 6
// speedup vs baseline: 5.3325x; 1.0375x over previous
#include <cuda_runtime.h>
#include <cuda_fp16.h>
#include <cstdint>

// ---------------------------------------------------------------------------
// Problem constants
// ---------------------------------------------------------------------------
#define NNODES_MAX 8192
#define E_MAX      131072
#define EF_MAX     (E_MAX / 2)
#define HID        768
#define PPRODS     83
#define MSG        249
#define NDIM       3

// ---------------------------------------------------------------------------
// Scratch (static __device__ BSS)
// ---------------------------------------------------------------------------
__device__ __half g_h1h[(size_t)EF_MAX * HID];   // 96 MB fp16
__device__ __half g_h2h[(size_t)EF_MAX * HID];   // 96 MB fp16
__device__ float  g_prods[(size_t)EF_MAX * PPRODS];
__device__ float  g_agg[NNODES_MAX * NDIM];
__device__ __half g_w2t[HID * HID];              // mW2^T [768][768] fp16
__device__ __half g_w3t[MSG * HID];              // mW3^T [249][768] fp16
__device__ int    g_fwd_e[EF_MAX];
__device__ int    g_fwd_src[EF_MAX];
__device__ int    g_fwd_dst[EF_MAX];
__device__ int    g_cnt;

__device__ __forceinline__ float leaky(float v) { return v > 0.f ? v : 0.01f * v; }

__device__ __forceinline__ uint32_t smem_u32(const void* p) {
    uint32_t a;
    asm("{ .reg .u64 t; cvta.to.shared.u64 t, %1; cvt.u32.u64 %0, t; }" : "=r"(a) : "l"(p));
    return a;
}

__device__ __forceinline__ void cpa16(uint32_t dst, const void* src, int valid) {
    int sz = valid ? 16 : 0;
    asm volatile("cp.async.cg.shared.global [%0], [%1], 16, %2;"
                 :: "r"(dst), "l"(src), "r"(sz));
}
__device__ __forceinline__ void cpa_commit() {
    asm volatile("cp.async.commit_group;" ::: "memory");
}
__device__ __forceinline__ void cpa_wait1() {
    asm volatile("cp.async.wait_group 1;" ::: "memory");
}

__device__ __forceinline__ void ldm_x4(uint32_t addr, uint32_t* r) {
    asm volatile("ldmatrix.sync.aligned.m8n8.x4.shared.b16 {%0,%1,%2,%3}, [%4];"
                 : "=r"(r[0]), "=r"(r[1]), "=r"(r[2]), "=r"(r[3]) : "r"(addr));
}

__device__ __forceinline__ void mma16816(float* c, const uint32_t* a, const uint32_t* b) {
    asm volatile(
        "mma.sync.aligned.m16n8k16.row.col.f32.f16.f16.f32 "
        "{%0,%1,%2,%3}, {%4,%5,%6,%7}, {%8,%9}, {%0,%1,%2,%3};"
        : "+f"(c[0]), "+f"(c[1]), "+f"(c[2]), "+f"(c[3])
        : "r"(a[0]), "r"(a[1]), "r"(a[2]), "r"(a[3]), "r"(b[0]), "r"(b[1]));
}

// ---------------------------------------------------------------------------
// Small kernels
// ---------------------------------------------------------------------------
__global__ void k_zero(int nAgg) {
    int i = blockIdx.x * blockDim.x + threadIdx.x;
    if (i < nAgg) g_agg[i] = 0.f;
    if (i == 0) g_cnt = 0;
}

__global__ void k_compact(const int* __restrict__ src, const int* __restrict__ dst, int E) {
    int e = blockIdx.x * blockDim.x + threadIdx.x;
    if (e >= E) return;
    int s = src[e], d = dst[e];
    if (s < d) {
        int i = atomicAdd(&g_cnt, 1);
        if (i < EF_MAX) { g_fwd_e[i] = e; g_fwd_src[i] = s; g_fwd_dst[i] = d; }
    }
}

// h1 = fp16(leaky(edge_attr @ W1 + b1)); poly products
__global__ __launch_bounds__(256) void k_h1_prods(
    const float* __restrict__ edge_attr,
    const float* __restrict__ W1, const float* __restrict__ b1, int EF)
{
    __shared__ float sW1[6 * HID];
    __shared__ float sb1[HID];
    int tid = threadIdx.x;
    for (int i = tid; i < 6 * HID; i += blockDim.x) sW1[i] = W1[i];
    for (int i = tid; i < HID;     i += blockDim.x) sb1[i] = b1[i];
    __syncthreads();

    int warp = tid >> 5, lane = tid & 31;
    int s = blockIdx.x * 8 + warp;
    if (s >= EF) return;
    int e = g_fwd_e[s];

    float a[6];
#pragma unroll
    for (int i = 0; i < 6; i++) a[i] = edge_attr[e * 6 + i];

    __half* h1r = g_h1h + (size_t)s * HID;
    for (int j = lane; j < HID; j += 32) {
        float acc = sb1[j];
#pragma unroll
        for (int i = 0; i < 6; i++) acc += a[i] * sW1[i * HID + j];
        h1r[j] = __float2half(leaky(acc));
    }

    if (lane == 0) {
        float* pp = g_prods + (size_t)s * PPRODS;
        int p = 0;
#pragma unroll
        for (int i = 0; i < 6; i++) pp[p++] = a[i];
#pragma unroll
        for (int i = 0; i < 6; i++)
            for (int j = i; j < 6; j++) pp[p++] = a[i] * a[j];
#pragma unroll
        for (int i = 0; i < 6; i++)
            for (int j = i; j < 6; j++)
                for (int k = j; k < 6; k++) pp[p++] = a[i] * a[j] * a[k];
    }
}

// tiled transpose + fp16 round: Wt[n*K_ld + k] = fp16(W[k*N + n])
__global__ void k_transpose(const float* __restrict__ W, __half* __restrict__ Wt,
                            int K, int N, int K_ld)
{
    __shared__ float t[32][33];
    int kb = blockIdx.y * 32, nb = blockIdx.x * 32;
    int tx = threadIdx.x, ty = threadIdx.y;
    for (int i = ty; i < 32; i += 8) {
        int k = kb + i, n = nb + tx;
        t[i][tx] = (k < K && n < N) ? W[(size_t)k * N + n] : 0.f;
    }
    __syncthreads();
    for (int i = ty; i < 32; i += 8) {
        int n = nb + i, k = kb + tx;
        if (n < N && k < K) Wt[(size_t)n * K_ld + k] = __float2half(t[tx][i]);
    }
}

// ---------------------------------------------------------------------------
// fp16 mma GEMM: BM=BN=128, BK=64, 3-stage cp.async, XOR-swizzled smem
// (row = 128B, chunk ^= row&7), ldmatrix + m16n8k16 f32 accum.
// 8 warps: wm=wid&3 (M), wn=wid>>2 (N); warp tile 32x64.
// mode 0: C f32       mode 1: C fp16 + leaky       mode 2: fused einsum+scatter
// ---------------------------------------------------------------------------
#define STG_B  16384              // bytes per stage per operand (128 rows x 128B)
#define NSTAGE 3
#define GEMM_SMEM_BYTES (NSTAGE * STG_B * 2)   // 98304

__global__ __launch_bounds__(256, 2) void gemm_fp16(
    const __half* __restrict__ A, const __half* __restrict__ Bt,
    const float* __restrict__ bias, void* __restrict__ Cout,
    int M, int N, int K, int mode)
{
    extern __shared__ __align__(128) char smraw[];
    const uint32_t aBase = smem_u32(smraw);
    const uint32_t bBase = aBase + NSTAGE * STG_B;

    const int tid  = threadIdx.x;
    const int wid  = tid >> 5;
    const int lane = tid & 31;
    const int g    = lane >> 2;
    const int tig  = lane & 3;
    const int wm   = wid & 3;
    const int wn   = wid >> 2;
    const int row0 = blockIdx.y * 128;
    const int col0 = blockIdx.x * 128;

    // staging: thread -> row r, half-row s (32 halves = 64B = 4 x 16B)
    const int r = tid >> 1;
    const int s = tid & 1;
    const int aV = (row0 + r) < M;
    const int bV = (col0 + r) < N;
    const __half* Ag = A  + (size_t)(row0 + r) * K + s * 32;
    const __half* Bg = Bt + (size_t)(col0 + r) * K + s * 32;

    uint32_t aDst[4], bDst[4];
    {
        uint32_t xorv = (uint32_t)((r & 7) << 4);
#pragma unroll
        for (int i = 0; i < 4; i++) {
            uint32_t off = ((uint32_t)(r * 128 + s * 64 + i * 16)) ^ xorv;
            aDst[i] = aBase + off;
            bDst[i] = bBase + off;
        }
    }

    // ldmatrix base components
    int aRow[2]; uint32_t aXor[2];
#pragma unroll
    for (int mi = 0; mi < 2; mi++) {
        int rw = wm * 32 + mi * 16 + (lane & 15);
        aRow[mi] = rw * 128;
        aXor[mi] = (uint32_t)((rw & 7) << 4);
    }
    const uint32_t aColp = (uint32_t)((lane >> 4) * 16);
    int bRow[4]; uint32_t bXor[4];
#pragma unroll
    for (int np = 0; np < 4; np++) {
        int rw = wn * 64 + np * 16 + (lane & 7) + ((lane >> 4) << 3);
        bRow[np] = rw * 128;
        bXor[np] = (uint32_t)((rw & 7) << 4);
    }
    const uint32_t bColp = (uint32_t)(((lane >> 3) & 1) * 16);

    float acc[2][8][4];
#pragma unroll
    for (int mi = 0; mi < 2; mi++)
#pragma unroll
        for (int ni = 0; ni < 8; ni++)
#pragma unroll
            for (int q = 0; q < 4; q++) acc[mi][ni][q] = 0.f;

    const int nCh = K / 64;

    // prologue: stage chunks 0, 1
#pragma unroll
    for (int c = 0; c < 2; c++) {
        uint32_t so = c * STG_B;
#pragma unroll
        for (int i = 0; i < 4; i++) {
            cpa16(aDst[i] + so, Ag + (size_t)c * 64 + i * 8, aV);
            cpa16(bDst[i] + so, Bg + (size_t)c * 64 + i * 8, bV);
        }
        cpa_commit();
    }

    for (int c = 0; c < nCh; ++c) {
        cpa_wait1();
        __syncthreads();

        if (c + 2 < nCh) {
            uint32_t so = ((c + 2) % NSTAGE) * STG_B;
#pragma unroll
            for (int i = 0; i < 4; i++) {
                cpa16(aDst[i] + so, Ag + (size_t)(c + 2) * 64 + i * 8, aV);
                cpa16(bDst[i] + so, Bg + (size_t)(c + 2) * 64 + i * 8, bV);
            }
        }
        cpa_commit();

        const uint32_t so = (c % NSTAGE) * STG_B;
#pragma unroll
        for (int ks = 0; ks < 4; ks++) {
            uint32_t a[2][4];
#pragma unroll
            for (int mi = 0; mi < 2; mi++)
                ldm_x4(aBase + so + (((uint32_t)aRow[mi] + aColp + ks * 32) ^ aXor[mi]), a[mi]);
            uint32_t b[4][4];
#pragma unroll
            for (int np = 0; np < 4; np++)
                ldm_x4(bBase + so + (((uint32_t)bRow[np] + bColp + ks * 32) ^ bXor[np]), b[np]);
#pragma unroll
            for (int mi = 0; mi < 2; mi++)
#pragma unroll
                for (int ni = 0; ni < 8; ni++)
                    mma16816(acc[mi][ni], a[mi], b[ni >> 1] + (ni & 1) * 2);
        }
    }

    // ----------------------------- epilogues -----------------------------
    if (mode == 2) {
        // fused einsum + antisymmetric scatter (no C store)
        float part[2][2][3];
#pragma unroll
        for (int mi = 0; mi < 2; mi++)
#pragma unroll
            for (int j = 0; j < 2; j++)
#pragma unroll
                for (int k = 0; k < 3; k++) part[mi][j][k] = 0.f;

#pragma unroll
        for (int mi = 0; mi < 2; mi++) {
            int r0 = row0 + wm * 32 + mi * 16 + g;
            int r1 = r0 + 8;
            const float* p0 = g_prods + (size_t)(r0 < M ? r0 : 0) * PPRODS;
            const float* p1 = g_prods + (size_t)(r1 < M ? r1 : 0) * PPRODS;
#pragma unroll
            for (int ni = 0; ni < 8; ni++) {
                int cc = col0 + wn * 64 + ni * 8 + tig * 2;
                if (cc < MSG) {
                    int k = (cc >= 2 * PPRODS) ? 2 : (cc >= PPRODS ? 1 : 0);
                    int p = cc - k * PPRODS;
                    float b0 = bias[cc];
                    part[mi][0][k] += (acc[mi][ni][0] + b0) * p0[p];
                    part[mi][1][k] += (acc[mi][ni][2] + b0) * p1[p];
                }
                int c1 = cc + 1;
                if (c1 < MSG) {
                    int k = (c1 >= 2 * PPRODS) ? 2 : (c1 >= PPRODS ? 1 : 0);
                    int p = c1 - k * PPRODS;
                    float b1 = bias[c1];
                    part[mi][0][k] += (acc[mi][ni][1] + b1) * p0[p];
                    part[mi][1][k] += (acc[mi][ni][3] + b1) * p1[p];
                }
            }
        }
        // quad reduction (tig lanes share rows)
#pragma unroll
        for (int mi = 0; mi < 2; mi++)
#pragma unroll
            for (int j = 0; j < 2; j++)
#pragma unroll
                for (int k = 0; k < 3; k++) {
                    float v = part[mi][j][k];
                    v += __shfl_xor_sync(0xffffffffu, v, 1);
                    v += __shfl_xor_sync(0xffffffffu, v, 2);
                    part[mi][j][k] = v;
                }
        if (tig == 0) {
#pragma unroll
            for (int mi = 0; mi < 2; mi++)
#pragma unroll
                for (int j = 0; j < 2; j++) {
                    int row = row0 + wm * 32 + mi * 16 + g + j * 8;
                    if (row < M) {
                        int d  = g_fwd_dst[row];
                        int sn = g_fwd_src[row];
#pragma unroll
                        for (int k = 0; k < 3; k++) {
                            atomicAdd(&g_agg[d  * 3 + k],  part[mi][j][k]);
                            atomicAdd(&g_agg[sn * 3 + k], -part[mi][j][k]);
                        }
                    }
                }
        }
        return;
    }

    float* Cf = (float*)Cout;
    __half* Ch = (__half*)Cout;
#pragma unroll
    for (int mi = 0; mi < 2; mi++) {
        int r0 = row0 + wm * 32 + mi * 16 + g;
        int r1 = r0 + 8;
#pragma unroll
        for (int ni = 0; ni < 8; ni++) {
            int cc = col0 + wn * 64 + ni * 8 + tig * 2;
            float b0 = (cc < N)     ? bias[cc]     : 0.f;
            float b1 = (cc + 1 < N) ? bias[cc + 1] : 0.f;
            float v0 = acc[mi][ni][0] + b0;
            float v1 = acc[mi][ni][1] + b1;
            float v2 = acc[mi][ni][2] + b0;
            float v3 = acc[mi][ni][3] + b1;
            if (mode == 1) {
                v0 = leaky(v0); v1 = leaky(v1); v2 = leaky(v2); v3 = leaky(v3);
                if (cc + 1 < N) {
                    if (r0 < M) *(__half2*)(Ch + (size_t)r0 * N + cc) = __floats2half2_rn(v0, v1);
                    if (r1 < M) *(__half2*)(Ch + (size_t)r1 * N + cc) = __floats2half2_rn(v2, v3);
                } else if (cc < N) {
                    if (r0 < M) Ch[(size_t)r0 * N + cc] = __float2half(v0);
                    if (r1 < M) Ch[(size_t)r1 * N + cc] = __float2half(v2);
                }
            } else {
                if (cc + 1 < N) {
                    if (r0 < M) *(float2*)(Cf + (size_t)r0 * N + cc) = make_float2(v0, v1);
                    if (r1 < M) *(float2*)(Cf + (size_t)r1 * N + cc) = make_float2(v2, v3);
                } else if (cc < N) {
                    if (r0 < M) Cf[(size_t)r0 * N + cc] = v0;
                    if (r1 < M) Cf[(size_t)r1 * N + cc] = v2;
                }
            }
        }
    }
}

// ---------------------------------------------------------------------------
// node update: LN + MLP 19->18->17->16
// ---------------------------------------------------------------------------
__global__ __launch_bounds__(128) void k_update(
    const float* __restrict__ x,
    const float* __restrict__ ln_g, const float* __restrict__ ln_b,
    const float* __restrict__ uW1, const float* __restrict__ ub1,
    const float* __restrict__ uW2, const float* __restrict__ ub2,
    const float* __restrict__ uW3, const float* __restrict__ ub3,
    float* __restrict__ out, int N)
{
    int n = blockIdx.x * blockDim.x + threadIdx.x;
    if (n >= N) return;

    float h[19];
#pragma unroll
    for (int i = 0; i < 16; i++) h[i] = x[n * 16 + i];
#pragma unroll
    for (int k = 0; k < 3; k++) h[16 + k] = g_agg[n * 3 + k];

    float mu = 0.f;
#pragma unroll
    for (int i = 0; i < 19; i++) mu += h[i];
    mu *= (1.f / 19.f);
    float var = 0.f;
#pragma unroll
    for (int i = 0; i < 19; i++) { float d = h[i] - mu; var += d * d; }
    var *= (1.f / 19.f);
    float rstd = rsqrtf(var + 1e-5f);

    float hn[19];
#pragma unroll
    for (int i = 0; i < 19; i++) hn[i] = (h[i] - mu) * rstd * ln_g[i] + ln_b[i];

    float t1[18];
#pragma unroll
    for (int o = 0; o < 18; o++) {
        float acc = ub1[o];
#pragma unroll
        for (int i = 0; i < 19; i++) acc += hn[i] * uW1[i * 18 + o];
        t1[o] = leaky(acc);
    }
    float t2[17];
#pragma unroll
    for (int o = 0; o < 17; o++) {
        float acc = ub2[o];
#pragma unroll
        for (int i = 0; i < 18; i++) acc += t1[i] * uW2[i * 17 + o];
        t2[o] = leaky(acc);
    }
#pragma unroll
    for (int o = 0; o < 16; o++) {
        float acc = ub3[o];
#pragma unroll
        for (int i = 0; i < 17; i++) acc += t2[i] * uW3[i * 16 + o];
        out[n * 16 + o] = acc;
    }
}

// ---------------------------------------------------------------------------
// launch
// ---------------------------------------------------------------------------
extern "C" void kernel_launch(void* const* d_in, const int* in_sizes, int n_in,
                              void* d_out, int out_size)
{
    const float* x    = (const float*)d_in[0];
    const float* ea   = (const float*)d_in[1];
    const float* mW1  = (const float*)d_in[2];
    const float* mb1  = (const float*)d_in[3];
    const float* mW2  = (const float*)d_in[4];
    const float* mb2  = (const float*)d_in[5];
    const float* mW3  = (const float*)d_in[6];
    const float* mb3  = (const float*)d_in[7];
    const float* ln_g = (const float*)d_in[8];
    const float* ln_b = (const float*)d_in[9];
    const float* uW1  = (const float*)d_in[10];
    const float* ub1  = (const float*)d_in[11];
    const float* uW2  = (const float*)d_in[12];
    const float* ub2  = (const float*)d_in[13];
    const float* uW3  = (const float*)d_in[14];
    const float* ub3  = (const float*)d_in[15];
    const int*   ei   = (const int*)d_in[16];
    float* out = (float*)d_out;

    const int N  = in_sizes[0] / 16;
    const int E  = in_sizes[1] / 6;
    int EF = E / 2;
    if (EF > EF_MAX) EF = EF_MAX;

    const int* src = ei;
    const int* dst = ei + E;

    __half *p_h1, *p_h2, *p_w2t, *p_w3t;
    cudaGetSymbolAddress((void**)&p_h1,  g_h1h);
    cudaGetSymbolAddress((void**)&p_h2,  g_h2h);
    cudaGetSymbolAddress((void**)&p_w2t, g_w2t);
    cudaGetSymbolAddress((void**)&p_w3t, g_w3t);

    cudaFuncSetAttribute(gemm_fp16, cudaFuncAttributeMaxDynamicSharedMemorySize,
                         GEMM_SMEM_BYTES);

    {
        int n = N * 3;
        k_zero<<<(n + 255) / 256, 256>>>(n);
    }
    k_compact<<<(E + 255) / 256, 256>>>(src, dst, E);

    {
        dim3 blk(32, 8);
        k_transpose<<<dim3(HID / 32, HID / 32), blk>>>(mW2, p_w2t, HID, HID, HID);
        k_transpose<<<dim3((MSG + 31) / 32, HID / 32), blk>>>(mW3, p_w3t, HID, MSG, HID);
    }

    k_h1_prods<<<(EF + 7) / 8, 256>>>(ea, mW1, mb1, EF);

    int Mtiles = (EF + 127) / 128;
    // GEMM2: h2 = fp16(leaky(h1 @ W2 + b2))    [EF,768]x[768,768]
    gemm_fp16<<<dim3(HID / 128, Mtiles), 256, GEMM_SMEM_BYTES>>>(
        p_h1, p_w2t, mb2, p_h2, EF, HID, HID, 1);
    // GEMM3 fused: einsum + antisymmetric scatter, no C output
    gemm_fp16<<<dim3((MSG + 127) / 128, Mtiles), 256, GEMM_SMEM_BYTES>>>(
        p_h2, p_w3t, mb3, nullptr, EF, MSG, HID, 2);

    k_update<<<(N + 127) / 128, 128>>>(x, ln_g, ln_b, uW1, ub1, uW2, ub2, uW3, ub3, out, N);
}